// round 15
// baseline (speedup 1.0000x reference)
#include <cuda_runtime.h>
#include <cuda_fp16.h>
#include <cstdint>

// Problem constants
#define B_   8
#define N_   4096
#define C_   1536
#define H_   24
#define R_   8
#define M_   192
#define SCALE_ 0.125f

// Scratch (static device globals)
__device__ float    g_Q[B_ * R_ * C_];                 // atomically accumulated
__device__ __half   g_QK16[B_ * M_ * C_];              // q@Wk, fp16
__device__ float    g_S[(size_t)B_ * M_ * N_];         // scores f32
__device__ __half   g_P16[(size_t)B_ * M_ * N_];       // softmax probs fp16
__device__ float    g_AX[B_ * M_ * C_];                // P @ x (split-K accumulated)
__device__ float    g_XCLS[B_ * R_ * C_];              // atomically accumulated
__device__ __half   g_x16[(size_t)B_ * N_ * C_];       // x fp16

// ---------------------------------------------------------------------------
// helpers
// ---------------------------------------------------------------------------
#define CPA(dst, src) asm volatile("cp.async.cg.shared.global [%0], [%1], 16;" :: "r"(dst), "l"(src))
#define CPCOMMIT()    asm volatile("cp.async.commit_group;")
#define CPWAIT0()     asm volatile("cp.async.wait_group 0;")
#define CPWAIT1()     asm volatile("cp.async.wait_group 1;")

#define LDSM4(r0, r1, r2, r3, addr) \
    asm volatile("ldmatrix.sync.aligned.m8n8.x4.shared.b16 {%0,%1,%2,%3}, [%4];" \
                 : "=r"(r0), "=r"(r1), "=r"(r2), "=r"(r3) : "r"(addr))
#define LDSM4T(r0, r1, r2, r3, addr) \
    asm volatile("ldmatrix.sync.aligned.m8n8.x4.trans.shared.b16 {%0,%1,%2,%3}, [%4];" \
                 : "=r"(r0), "=r"(r1), "=r"(r2), "=r"(r3) : "r"(addr))

__device__ __forceinline__ void mma16(float* c, const uint32_t* a, const uint32_t* b) {
    asm volatile(
        "mma.sync.aligned.m16n8k16.row.col.f32.f16.f16.f32 "
        "{%0,%1,%2,%3}, {%4,%5,%6,%7}, {%8,%9}, {%0,%1,%2,%3};"
        : "+f"(c[0]), "+f"(c[1]), "+f"(c[2]), "+f"(c[3])
        : "r"(a[0]), "r"(a[1]), "r"(a[2]), "r"(a[3]), "r"(b[0]), "r"(b[1]));
}

__device__ __forceinline__ float warpMax(float v) {
    #pragma unroll
    for (int o = 16; o; o >>= 1) v = fmaxf(v, __shfl_xor_sync(0xffffffffu, v, o));
    return v;
}
__device__ __forceinline__ float warpSum(float v) {
    #pragma unroll
    for (int o = 16; o; o >>= 1) v += __shfl_xor_sync(0xffffffffu, v, o);
    return v;
}

// ---------------------------------------------------------------------------
// conv range worker: convert x[f32] -> g_x16 over uint4 indices [lo, hi)
// ---------------------------------------------------------------------------
__device__ __forceinline__ void conv_range(const float* __restrict__ x,
                                           size_t lo, size_t hi,
                                           int rb, int nb, int t) {
    for (size_t i = lo + (size_t)rb * 256 + t; i < hi; i += (size_t)nb * 256) {
        float4 v0 = ((const float4*)x)[i * 2];
        float4 v1 = ((const float4*)x)[i * 2 + 1];
        __half h[8];
        h[0] = __float2half_rn(v0.x); h[1] = __float2half_rn(v0.y);
        h[2] = __float2half_rn(v0.z); h[3] = __float2half_rn(v0.w);
        h[4] = __float2half_rn(v1.x); h[5] = __float2half_rn(v1.y);
        h[6] = __float2half_rn(v1.z); h[7] = __float2half_rn(v1.w);
        ((uint4*)g_x16)[i] = *(uint4*)h;
    }
}

#define CONV_TOTAL ((size_t)B_ * N_ * C_ / 8)
#define CONV_HALF  (CONV_TOTAL / 2)

// ---------------------------------------------------------------------------
// k_zq: zero g_Q (must precede k_q atomics)
// ---------------------------------------------------------------------------
__global__ __launch_bounds__(256) void k_zq() {
    int i = blockIdx.x * 256 + threadIdx.x;
    ((float4*)g_Q)[i] = make_float4(0.f, 0.f, 0.f, 0.f);
}

// ---------------------------------------------------------------------------
// k_p2: union launch — conv_lo (1280 blocks) | k_q (768 blocks) | zero_rest (64)
// ---------------------------------------------------------------------------
#define P2_CONV 1280
#define P2_Q    768
#define P2_Z    64
#define QK_SLICE (C_ / 16)   // 96
__global__ __launch_bounds__(256) void k_p2(const float* __restrict__ x,
                                            const float* __restrict__ Wq,
                                            float* __restrict__ out) {
    int bid = blockIdx.x, t = threadIdx.x;
    if (bid < P2_CONV) {
        conv_range(x, 0, CONV_HALF, bid, P2_CONV, t);
        return;
    }
    bid -= P2_CONV;
    if (bid < P2_Q) {
        __shared__ float xs[R_ * QK_SLICE];
        int cpt = bid % 6, b = (bid / 6) % 8, kc = bid / 48;
        int k0 = kc * QK_SLICE;
        if (t < R_ * QK_SLICE / 4) {
            int r = t / (QK_SLICE / 4), c4 = t % (QK_SLICE / 4);
            ((float4*)xs)[t] = *(const float4*)(x + ((size_t)(b * N_ + r)) * C_ + k0 + c4 * 4);
        }
        __syncthreads();
        int cp = cpt * 256 + t;
        const float4* wr = (const float4*)(Wq + (size_t)cp * C_ + k0);
        float acc[R_] = {};
        #pragma unroll 4
        for (int k4 = 0; k4 < QK_SLICE / 4; k4++) {
            float4 w = wr[k4];
            #pragma unroll
            for (int r = 0; r < R_; r++) {
                float4 a = ((const float4*)(xs + r * QK_SLICE))[k4];
                acc[r] += a.x * w.x + a.y * w.y + a.z * w.z + a.w * w.w;
            }
        }
        #pragma unroll
        for (int r = 0; r < R_; r++)
            atomicAdd(&g_Q[(b * R_ + r) * C_ + cp], acc[r] * SCALE_);
        return;
    }
    bid -= P2_Q;
    const float4 z = make_float4(0.f, 0.f, 0.f, 0.f);
    size_t stride = (size_t)P2_Z * 256;
    size_t t0 = (size_t)bid * 256 + t;
    for (size_t i = t0; i < (size_t)B_ * M_ * C_ / 4; i += stride) ((float4*)g_AX)[i] = z;
    for (size_t i = t0; i < (size_t)B_ * R_ * C_ / 4; i += stride) {
        ((float4*)g_XCLS)[i] = z;
        ((float4*)out)[i] = z;
    }
}

// ---------------------------------------------------------------------------
// k_p3: union launch — conv_hi (1280 blocks) | k_qk (576 blocks, 256 thr)
// ---------------------------------------------------------------------------
#define P3_CONV 1280
__global__ __launch_bounds__(256) void k_p3(const float* __restrict__ x,
                                            const float* __restrict__ Wk) {
    int bid = blockIdx.x, t = threadIdx.x;
    if (bid < P3_CONV) {
        conv_range(x, CONV_HALF, CONV_TOTAL, bid, P3_CONV, t);
        return;
    }
    bid -= P3_CONV;
    __shared__ float Qs[16][64];
    int cx = bid % 6, h = (bid / 6) % 24, qt = bid / 144;
    for (int i = t; i < 16 * 64; i += 256) {
        int brl = i >> 6, d = i & 63;
        Qs[brl][d] = g_Q[(qt * 16 + brl) * C_ + h * 64 + d];
    }
    __syncthreads();
    int c = cx * 256 + t;
    float acc[16] = {};
    #pragma unroll 4
    for (int d = 0; d < 64; d++) {
        float w = Wk[(size_t)(h * 64 + d) * C_ + c];
        #pragma unroll
        for (int brl = 0; brl < 16; brl++) acc[brl] += Qs[brl][d] * w;
    }
    #pragma unroll
    for (int brl = 0; brl < 16; brl++) {
        int br = qt * 16 + brl;
        int b = br >> 3, r = br & 7;
        g_QK16[((size_t)(b * M_ + h * 8 + r)) * C_ + c] = __float2half_rn(acc[brl]);
    }
}

// ---------------------------------------------------------------------------
// k_scores: S = QK16 . x16^T   fp16 mma, BM=192, BN=128, BK=64, 3-stage depth-2
// 384 threads: 12 warps (3m x 4n), warp 64x32. 1 CTA/SM (138KB smem).
// BN=128 halves A-operand L2 re-read traffic (the measured bottleneck).
// ---------------------------------------------------------------------------
#define SC_STAGE 46080   // A 192*72*2 (27648) + B 128*72*2 (18432)
#define SC_BOFF  27648
__global__ __launch_bounds__(384, 1) void k_scores() {
    extern __shared__ char smem[];
    uint32_t sb = (uint32_t)__cvta_generic_to_shared(smem);
    int b = blockIdx.z, nt = blockIdx.x;
    int tid = threadIdx.x, lane = tid & 31, warp = tid >> 5;
    int g = lane >> 2, q = lane & 3;
    int m0 = (warp >> 2) * 64, n0 = (warp & 3) * 32;

    const __half* Ab = g_QK16 + (size_t)b * M_ * C_;
    const __half* Bb = g_x16 + ((size_t)(b * N_ + nt * 128)) * C_;

    const uint32_t aoff = (uint32_t)((m0 + (lane & 7) + ((lane >> 3) & 1) * 8) * 72
                                     + (lane >> 4) * 8) * 2;
    const uint32_t boff = (uint32_t)((n0 + (lane & 7) + ((lane >> 4) & 1) * 8) * 72
                                     + ((lane >> 3) & 1) * 8) * 2;

    float acc[4][4][4] = {};
    uint32_t afr[2][4][4], bfr[2][2][4];

    #define SC_LOAD(st, itv)                                                     \
        do {                                                                     \
            uint32_t a0 = sb + (st) * SC_STAGE;                                  \
            uint32_t b0 = a0 + SC_BOFF;                                          \
            int kb = (itv) * 64;                                                 \
            for (int i = tid; i < 2560; i += 384) {                              \
                if (i < 1536) {                                                  \
                    int row = i >> 3, ch = i & 7;                                \
                    CPA(a0 + (row * 72 + ch * 8) * 2,                            \
                        Ab + (size_t)row * C_ + kb + ch * 8);                    \
                } else {                                                         \
                    int j = i - 1536;                                            \
                    int row = j >> 3, ch = j & 7;                                \
                    CPA(b0 + (row * 72 + ch * 8) * 2,                            \
                        Bb + (size_t)row * C_ + kb + ch * 8);                    \
                }                                                                \
            }                                                                    \
            CPCOMMIT();                                                          \
        } while (0)

    #define SC_FRAG(slot, aB, bB, ks)                                            \
        do {                                                                     \
            _Pragma("unroll")                                                    \
            for (int mi = 0; mi < 4; mi++)                                       \
                LDSM4(afr[slot][mi][0], afr[slot][mi][1],                        \
                      afr[slot][mi][2], afr[slot][mi][3],                        \
                      (aB) + aoff + (mi * 16 * 72 + (ks)) * 2);                  \
            _Pragma("unroll")                                                    \
            for (int bi = 0; bi < 2; bi++)                                       \
                LDSM4(bfr[slot][bi][0], bfr[slot][bi][1],                        \
                      bfr[slot][bi][2], bfr[slot][bi][3],                        \
                      (bB) + boff + (bi * 16 * 72 + (ks)) * 2);                  \
        } while (0)

    const int NK = C_ / 64;  // 24
    SC_LOAD(0, 0); SC_LOAD(1, 1);

    for (int it = 0; it < NK; ++it) {
        if (it < NK - 1) CPWAIT1();
        else             CPWAIT0();
        __syncthreads();
        int nx = it + 2;
        if (nx < NK) SC_LOAD(nx % 3, nx);

        uint32_t aB = sb + (it % 3) * SC_STAGE;
        uint32_t bB = aB + SC_BOFF;

        SC_FRAG(0, aB, bB, 0);
        #pragma unroll
        for (int ks = 0; ks < 64; ks += 16) {
            int cur = (ks >> 4) & 1;
            if (ks + 16 < 64) SC_FRAG(cur ^ 1, aB, bB, ks + 16);
            #pragma unroll
            for (int mi = 0; mi < 4; mi++)
                #pragma unroll
                for (int ni = 0; ni < 4; ni++)
                    mma16(acc[mi][ni], afr[cur][mi], &bfr[cur][ni >> 1][(ni & 1) * 2]);
        }
    }
    #undef SC_FRAG
    #undef SC_LOAD

    float* Cb = g_S + (size_t)b * M_ * N_ + (size_t)nt * 128;
    #pragma unroll
    for (int mi = 0; mi < 4; mi++)
        #pragma unroll
        for (int ni = 0; ni < 4; ni++) {
            int row = m0 + mi * 16 + g;
            int col = n0 + ni * 8 + q * 2;
            *(float2*)(Cb + (size_t)row * N_ + col)       = make_float2(acc[mi][ni][0], acc[mi][ni][1]);
            *(float2*)(Cb + (size_t)(row + 8) * N_ + col) = make_float2(acc[mi][ni][2], acc[mi][ni][3]);
        }
}

// ---------------------------------------------------------------------------
// k_softmax: masked softmax; reads g_S f32, writes g_P16 fp16
// ---------------------------------------------------------------------------
__global__ __launch_bounds__(256) void k_softmax(const int* __restrict__ mask) {
    int row = blockIdx.x;
    int b = row / M_, m = row % M_, r = m & 7;
    const float* S = g_S + (size_t)row * N_;
    __half* P = g_P16 + (size_t)row * N_;
    const int* mrow = mask + ((size_t)(b * R_ + r)) * (N_ - R_);
    int tid = threadIdx.x;

    float vals[16];
    float mx = -1e30f;
    #pragma unroll
    for (int i = 0; i < 16; i++) {
        int n = i * 256 + tid;
        float s = S[n];
        bool valid = (n < R_) ? (n == r) : (mrow[n - R_] != 0);
        s = valid ? s : -1e30f;
        vals[i] = s;
        mx = fmaxf(mx, s);
    }
    __shared__ float smx[8], ssm[8];
    float wmx = warpMax(mx);
    if ((tid & 31) == 0) smx[tid >> 5] = wmx;
    __syncthreads();
    float bm = smx[0];
    #pragma unroll
    for (int j = 1; j < 8; j++) bm = fmaxf(bm, smx[j]);

    float sum = 0.f;
    #pragma unroll
    for (int i = 0; i < 16; i++) {
        vals[i] = expf(vals[i] - bm);
        sum += vals[i];
    }
    float wsm = warpSum(sum);
    if ((tid & 31) == 0) ssm[tid >> 5] = wsm;
    __syncthreads();
    float tot = 0.f;
    #pragma unroll
    for (int j = 0; j < 8; j++) tot += ssm[j];
    float inv = 1.0f / tot;
    #pragma unroll
    for (int i = 0; i < 16; i++) P[i * 256 + tid] = __float2half_rn(vals[i] * inv);
}

// ---------------------------------------------------------------------------
// k_ax: AX[m,c] += sum_{n in split} P16[m,n] * x16[n,c]   (split-K x4)
// BM=192, BN=128 (c), BK=64 (tokens), 3-stage depth-2, fragment double-buffer.
// 384 threads: 12 warps (3m x 4n), warp 64x32. grid (12 c-tiles, 4, 8).
// ---------------------------------------------------------------------------
#define AX_STAGE 45056   // A 192*72*2 (27648) + B 64*136*2 (17408)
#define AX_BOFF  27648
#define AX_SPLIT 4
__global__ __launch_bounds__(384, 1) void k_ax() {
    extern __shared__ char smem[];
    uint32_t sb = (uint32_t)__cvta_generic_to_shared(smem);
    int b = blockIdx.z, nt = blockIdx.x, kc = blockIdx.y;
    int tid = threadIdx.x, lane = tid & 31, warp = tid >> 5;
    int g = lane >> 2, q = lane & 3;
    int m0 = (warp >> 2) * 64, n0 = (warp & 3) * 32;

    const int K0 = kc * (N_ / AX_SPLIT);
    const __half* Ab = g_P16 + (size_t)b * M_ * N_ + K0;
    const __half* Bx = g_x16 + (size_t)b * N_ * C_ + (size_t)K0 * C_ + nt * 128;

    const uint32_t aoff = (uint32_t)((m0 + (lane & 7) + ((lane >> 3) & 1) * 8) * 72
                                     + (lane >> 4) * 8) * 2;
    // trans B: rows = k (tokens), cols = n (136-half row stride)
    const uint32_t boff = (uint32_t)(((lane & 7) + ((lane >> 3) & 1) * 8) * 136
                                     + n0 + ((lane >> 4) & 1) * 8) * 2;

    float acc[4][4][4] = {};
    uint32_t afr[2][4][4], bfr[2][2][4];

    #define AX_LOAD(st, itv)                                                     \
        do {                                                                     \
            uint32_t a0 = sb + (st) * AX_STAGE;                                  \
            uint32_t b0 = a0 + AX_BOFF;                                          \
            int kb = (itv) * 64;                                                 \
            for (int i = tid; i < 2560; i += 384) {                              \
                if (i < 1536) {                                                  \
                    int row = i >> 3, ch = i & 7;                                \
                    CPA(a0 + (row * 72 + ch * 8) * 2,                            \
                        Ab + (size_t)row * N_ + kb + ch * 8);                    \
                } else {                                                         \
                    int j = i - 1536;                                            \
                    int row = j >> 4, ch = j & 15;                               \
                    CPA(b0 + (row * 136 + ch * 8) * 2,                           \
                        Bx + (size_t)(kb + row) * C_ + ch * 8);                  \
                }                                                                \
            }                                                                    \
            CPCOMMIT();                                                          \
        } while (0)

    #define AX_FRAG(slot, aB, bB, ks)                                            \
        do {                                                                     \
            _Pragma("unroll")                                                    \
            for (int mi = 0; mi < 4; mi++)                                       \
                LDSM4(afr[slot][mi][0], afr[slot][mi][1],                        \
                      afr[slot][mi][2], afr[slot][mi][3],                        \
                      (aB) + aoff + (mi * 16 * 72 + (ks)) * 2);                  \
            _Pragma("unroll")                                                    \
            for (int bi = 0; bi < 2; bi++)                                       \
                LDSM4T(bfr[slot][bi][0], bfr[slot][bi][1],                       \
                       bfr[slot][bi][2], bfr[slot][bi][3],                       \
                       (bB) + boff + ((ks) * 136 + bi * 16) * 2);                \
        } while (0)

    const int NK = (N_ / AX_SPLIT) / 64;  // 16
    AX_LOAD(0, 0); AX_LOAD(1, 1);

    for (int it = 0; it < NK; ++it) {
        if (it < NK - 1) CPWAIT1();
        else             CPWAIT0();
        __syncthreads();
        int nx = it + 2;
        if (nx < NK) AX_LOAD(nx % 3, nx);

        uint32_t aB = sb + (it % 3) * AX_STAGE;
        uint32_t bB = aB + AX_BOFF;

        AX_FRAG(0, aB, bB, 0);
        #pragma unroll
        for (int ks = 0; ks < 64; ks += 16) {
            int cur = (ks >> 4) & 1;
            if (ks + 16 < 64) AX_FRAG(cur ^ 1, aB, bB, ks + 16);
            #pragma unroll
            for (int mi = 0; mi < 4; mi++)
                #pragma unroll
                for (int ni = 0; ni < 4; ni++)
                    mma16(acc[mi][ni], afr[cur][mi], &bfr[cur][ni >> 1][(ni & 1) * 2]);
        }
    }
    #undef AX_FRAG
    #undef AX_LOAD

    float* Cb = g_AX + (size_t)b * M_ * C_ + nt * 128;
    #pragma unroll
    for (int mi = 0; mi < 4; mi++)
        #pragma unroll
        for (int ni = 0; ni < 4; ni++) {
            int row = m0 + mi * 16 + g;
            int col = n0 + ni * 8 + q * 2;
            float* p0 = Cb + (size_t)row * C_ + col;
            float* p1 = Cb + (size_t)(row + 8) * C_ + col;
            atomicAdd(p0,     acc[mi][ni][0]);
            atomicAdd(p0 + 1, acc[mi][ni][1]);
            atomicAdd(p1,     acc[mi][ni][2]);
            atomicAdd(p1 + 1, acc[mi][ni][3]);
        }
}

// ---------------------------------------------------------------------------
// k_d1: XCLS[b,r,cc] += sum_{c in slice} AX[b, (cc/64)*8+r, c] * Wv[cc, c]
// K-split x16: grid (6, 8, 16). atomicAdd into zeroed g_XCLS.
// ---------------------------------------------------------------------------
__global__ __launch_bounds__(256) void k_d1(const float* __restrict__ Wv) {
    int b = blockIdx.y, kc = blockIdx.z, t = threadIdx.x;
    int k0 = kc * QK_SLICE;
    int cc = blockIdx.x * 256 + t;
    int h = cc >> 6;
    const float4* wr = (const float4*)(Wv + (size_t)cc * C_ + k0);
    const float4* ax[R_];
    #pragma unroll
    for (int r = 0; r < R_; r++)
        ax[r] = (const float4*)(g_AX + ((size_t)b * M_ + h * 8 + r) * C_ + k0);
    float acc[R_] = {};
    #pragma unroll 4
    for (int k4 = 0; k4 < QK_SLICE / 4; k4++) {
        float4 w = wr[k4];
        #pragma unroll
        for (int r = 0; r < R_; r++) {
            float4 a = ax[r][k4];
            acc[r] += a.x * w.x + a.y * w.y + a.z * w.z + a.w * w.w;
        }
    }
    #pragma unroll
    for (int r = 0; r < R_; r++)
        atomicAdd(&g_XCLS[(b * R_ + r) * C_ + cc], acc[r]);
}

// ---------------------------------------------------------------------------
// k_d2: out[b,r,c'] += sum_{cc in slice} XCLS[b,r,cc] * Wp[c',cc]  (+bias on kc0)
// K-split x16: grid (6, 8, 16). atomicAdd into zeroed out.
// ---------------------------------------------------------------------------
__global__ __launch_bounds__(256) void k_d2(const float* __restrict__ Wp,
                                            const float* __restrict__ bp,
                                            float* __restrict__ out) {
    int b = blockIdx.y, kc = blockIdx.z, t = threadIdx.x;
    int k0 = kc * QK_SLICE;
    int cp = blockIdx.x * 256 + t;
    const float4* wr = (const float4*)(Wp + (size_t)cp * C_ + k0);
    const float4* xc[R_];
    #pragma unroll
    for (int r = 0; r < R_; r++)
        xc[r] = (const float4*)(g_XCLS + (size_t)(b * R_ + r) * C_ + k0);
    float acc[R_] = {};
    #pragma unroll 4
    for (int k4 = 0; k4 < QK_SLICE / 4; k4++) {
        float4 w = wr[k4];
        #pragma unroll
        for (int r = 0; r < R_; r++) {
            float4 a = xc[r][k4];
            acc[r] += a.x * w.x + a.y * w.y + a.z * w.z + a.w * w.w;
        }
    }
    float bias = (kc == 0) ? bp[cp] : 0.f;
    #pragma unroll
    for (int r = 0; r < R_; r++)
        atomicAdd(&out[((size_t)(b * R_ + r)) * C_ + cp], acc[r] + bias);
}

// ---------------------------------------------------------------------------
// launch
// ---------------------------------------------------------------------------
extern "C" void kernel_launch(void* const* d_in, const int* in_sizes, int n_in,
                              void* d_out, int out_size) {
    const float* x    = (const float*)d_in[0];
    const int*   mask = (const int*)d_in[1];
    const float* Wq   = (const float*)d_in[2];
    const float* Wk   = (const float*)d_in[3];
    const float* Wv   = (const float*)d_in[4];
    const float* Wp   = (const float*)d_in[5];
    const float* bp   = (const float*)d_in[6];
    float* out = (float*)d_out;

    const int SC_SMEM = 3 * SC_STAGE;  // 138240
    const int AX_SMEM = 3 * AX_STAGE;  // 135168
    cudaFuncSetAttribute(k_scores, cudaFuncAttributeMaxDynamicSharedMemorySize, SC_SMEM);
    cudaFuncSetAttribute(k_ax,     cudaFuncAttributeMaxDynamicSharedMemorySize, AX_SMEM);

    k_zq     <<<96, 256>>>();
    k_p2     <<<P2_CONV + P2_Q + P2_Z, 256>>>(x, Wq, out);
    k_p3     <<<P3_CONV + 576, 256>>>(x, Wk);
    k_scores <<<dim3(N_ / 128, 1, B_), 384, SC_SMEM>>>();
    k_softmax<<<B_ * M_, 256>>>(mask);
    k_ax     <<<dim3(C_ / 128, AX_SPLIT, B_), 384, AX_SMEM>>>();
    k_d1     <<<dim3(C_ / 256, B_, 16), 256>>>(Wv);
    k_d2     <<<dim3(C_ / 256, B_, 16), 256>>>(Wp, bp, out);
}

// round 16
// speedup vs baseline: 1.0380x; 1.0380x over previous
#include <cuda_runtime.h>
#include <cuda_fp16.h>
#include <cstdint>

// Problem constants
#define B_   8
#define N_   4096
#define C_   1536
#define H_   24
#define R_   8
#define M_   192
#define SCALE_ 0.125f

// Scratch (static device globals)
__device__ float    g_Qp[16 * B_ * R_ * C_];           // k_q partials (per K-slice)
__device__ __half   g_QK16[B_ * M_ * C_];              // q@Wk, fp16
__device__ float    g_S[(size_t)B_ * M_ * N_];         // scores f32
__device__ __half   g_P16[(size_t)B_ * M_ * N_];       // softmax probs fp16
__device__ float    g_AX[B_ * M_ * C_];                // P @ x (split-K accumulated)
__device__ float    g_XCLS[B_ * R_ * C_];              // atomically accumulated
__device__ __half   g_x16[(size_t)B_ * N_ * C_];       // x fp16

// ---------------------------------------------------------------------------
// helpers
// ---------------------------------------------------------------------------
#define CPA(dst, src) asm volatile("cp.async.cg.shared.global [%0], [%1], 16;" :: "r"(dst), "l"(src))
#define CPCOMMIT()    asm volatile("cp.async.commit_group;")
#define CPWAIT0()     asm volatile("cp.async.wait_group 0;")
#define CPWAIT1()     asm volatile("cp.async.wait_group 1;")

#define LDSM4(r0, r1, r2, r3, addr) \
    asm volatile("ldmatrix.sync.aligned.m8n8.x4.shared.b16 {%0,%1,%2,%3}, [%4];" \
                 : "=r"(r0), "=r"(r1), "=r"(r2), "=r"(r3) : "r"(addr))
#define LDSM4T(r0, r1, r2, r3, addr) \
    asm volatile("ldmatrix.sync.aligned.m8n8.x4.trans.shared.b16 {%0,%1,%2,%3}, [%4];" \
                 : "=r"(r0), "=r"(r1), "=r"(r2), "=r"(r3) : "r"(addr))

__device__ __forceinline__ void mma16(float* c, const uint32_t* a, const uint32_t* b) {
    asm volatile(
        "mma.sync.aligned.m16n8k16.row.col.f32.f16.f16.f32 "
        "{%0,%1,%2,%3}, {%4,%5,%6,%7}, {%8,%9}, {%0,%1,%2,%3};"
        : "+f"(c[0]), "+f"(c[1]), "+f"(c[2]), "+f"(c[3])
        : "r"(a[0]), "r"(a[1]), "r"(a[2]), "r"(a[3]), "r"(b[0]), "r"(b[1]));
}

__device__ __forceinline__ float warpMax(float v) {
    #pragma unroll
    for (int o = 16; o; o >>= 1) v = fmaxf(v, __shfl_xor_sync(0xffffffffu, v, o));
    return v;
}
__device__ __forceinline__ float warpSum(float v) {
    #pragma unroll
    for (int o = 16; o; o >>= 1) v += __shfl_xor_sync(0xffffffffu, v, o);
    return v;
}

// ---------------------------------------------------------------------------
// conv range worker: convert x[f32] -> g_x16 over uint4 indices [lo, hi)
// ---------------------------------------------------------------------------
__device__ __forceinline__ void conv_range(const float* __restrict__ x,
                                           size_t lo, size_t hi,
                                           int rb, int nb, int t) {
    for (size_t i = lo + (size_t)rb * 256 + t; i < hi; i += (size_t)nb * 256) {
        float4 v0 = ((const float4*)x)[i * 2];
        float4 v1 = ((const float4*)x)[i * 2 + 1];
        __half h[8];
        h[0] = __float2half_rn(v0.x); h[1] = __float2half_rn(v0.y);
        h[2] = __float2half_rn(v0.z); h[3] = __float2half_rn(v0.w);
        h[4] = __float2half_rn(v1.x); h[5] = __float2half_rn(v1.y);
        h[6] = __float2half_rn(v1.z); h[7] = __float2half_rn(v1.w);
        ((uint4*)g_x16)[i] = *(uint4*)h;
    }
}

#define CONV_TOTAL ((size_t)B_ * N_ * C_ / 8)
#define CONV_HALF  (CONV_TOTAL / 2)

// ---------------------------------------------------------------------------
// k_p2: union launch — conv_lo (1280 blocks) | k_q (768 blocks) | zero_rest (64)
// k_q writes per-slice partial buffers (no atomics, no pre-zero needed).
// ---------------------------------------------------------------------------
#define P2_CONV 1280
#define P2_Q    768
#define P2_Z    64
#define QK_SLICE (C_ / 16)   // 96
#define QP_STRIDE (B_ * R_ * C_)
__global__ __launch_bounds__(256) void k_p2(const float* __restrict__ x,
                                            const float* __restrict__ Wq,
                                            float* __restrict__ out) {
    int bid = blockIdx.x, t = threadIdx.x;
    if (bid < P2_CONV) {
        conv_range(x, 0, CONV_HALF, bid, P2_CONV, t);
        return;
    }
    bid -= P2_CONV;
    if (bid < P2_Q) {
        __shared__ float xs[R_ * QK_SLICE];
        int cpt = bid % 6, b = (bid / 6) % 8, kc = bid / 48;
        int k0 = kc * QK_SLICE;
        if (t < R_ * QK_SLICE / 4) {
            int r = t / (QK_SLICE / 4), c4 = t % (QK_SLICE / 4);
            ((float4*)xs)[t] = *(const float4*)(x + ((size_t)(b * N_ + r)) * C_ + k0 + c4 * 4);
        }
        __syncthreads();
        int cp = cpt * 256 + t;
        const float4* wr = (const float4*)(Wq + (size_t)cp * C_ + k0);
        float acc[R_] = {};
        #pragma unroll 4
        for (int k4 = 0; k4 < QK_SLICE / 4; k4++) {
            float4 w = wr[k4];
            #pragma unroll
            for (int r = 0; r < R_; r++) {
                float4 a = ((const float4*)(xs + r * QK_SLICE))[k4];
                acc[r] += a.x * w.x + a.y * w.y + a.z * w.z + a.w * w.w;
            }
        }
        #pragma unroll
        for (int r = 0; r < R_; r++)
            g_Qp[(size_t)kc * QP_STRIDE + (b * R_ + r) * C_ + cp] = acc[r] * SCALE_;
        return;
    }
    bid -= P2_Q;
    const float4 z = make_float4(0.f, 0.f, 0.f, 0.f);
    size_t stride = (size_t)P2_Z * 256;
    size_t t0 = (size_t)bid * 256 + t;
    for (size_t i = t0; i < (size_t)B_ * M_ * C_ / 4; i += stride) ((float4*)g_AX)[i] = z;
    for (size_t i = t0; i < (size_t)B_ * R_ * C_ / 4; i += stride) {
        ((float4*)g_XCLS)[i] = z;
        ((float4*)out)[i] = z;
    }
}

// ---------------------------------------------------------------------------
// k_p3: union launch — conv_hi (1280 blocks) | k_qk (576 blocks, 256 thr)
// k_qk sums the 16 k_q partials while staging Q into smem.
// ---------------------------------------------------------------------------
#define P3_CONV 1280
__global__ __launch_bounds__(256) void k_p3(const float* __restrict__ x,
                                            const float* __restrict__ Wk) {
    int bid = blockIdx.x, t = threadIdx.x;
    if (bid < P3_CONV) {
        conv_range(x, CONV_HALF, CONV_TOTAL, bid, P3_CONV, t);
        return;
    }
    bid -= P3_CONV;
    __shared__ float Qs[16][64];
    int cx = bid % 6, h = (bid / 6) % 24, qt = bid / 144;
    for (int i = t; i < 16 * 64; i += 256) {
        int brl = i >> 6, d = i & 63;
        const float* base = g_Qp + (size_t)(qt * 16 + brl) * C_ + h * 64 + d;
        float s = 0.f;
        #pragma unroll
        for (int kc = 0; kc < 16; kc++) s += base[(size_t)kc * QP_STRIDE];
        Qs[brl][d] = s;
    }
    __syncthreads();
    int c = cx * 256 + t;
    float acc[16] = {};
    #pragma unroll 4
    for (int d = 0; d < 64; d++) {
        float w = Wk[(size_t)(h * 64 + d) * C_ + c];
        #pragma unroll
        for (int brl = 0; brl < 16; brl++) acc[brl] += Qs[brl][d] * w;
    }
    #pragma unroll
    for (int brl = 0; brl < 16; brl++) {
        int br = qt * 16 + brl;
        int b = br >> 3, r = br & 7;
        g_QK16[((size_t)(b * M_ + h * 8 + r)) * C_ + c] = __float2half_rn(acc[brl]);
    }
}

// ---------------------------------------------------------------------------
// k_scores: S = QK16 . x16^T   fp16 mma, BM=192, BN=64, BK=64, 3-stage depth-2
// 192 threads: 6 warps (3m x 2n), warp 64x32. 2 CTAs/SM. Fragment double-buffer.
// (Proven best config — round 14, 318.8us.)
// ---------------------------------------------------------------------------
#define SC_STAGE 36864   // (192+64) rows * 72 halfs * 2B
#define SC_BOFF  27648   // A = 192*72*2
__global__ __launch_bounds__(192, 2) void k_scores() {
    extern __shared__ char smem[];
    uint32_t sb = (uint32_t)__cvta_generic_to_shared(smem);
    int b = blockIdx.z, nt = blockIdx.x;
    int tid = threadIdx.x, lane = tid & 31, warp = tid >> 5;
    int g = lane >> 2, q = lane & 3;
    int m0 = (warp >> 1) * 64, n0 = (warp & 1) * 32;

    const __half* Ab = g_QK16 + (size_t)b * M_ * C_;
    const __half* Bb = g_x16 + ((size_t)(b * N_ + nt * 64)) * C_;

    const uint32_t aoff = (uint32_t)((m0 + (lane & 7) + ((lane >> 3) & 1) * 8) * 72
                                     + (lane >> 4) * 8) * 2;
    const uint32_t boff = (uint32_t)((n0 + (lane & 7) + ((lane >> 4) & 1) * 8) * 72
                                     + ((lane >> 3) & 1) * 8) * 2;

    float acc[4][4][4] = {};
    uint32_t afr[2][4][4], bfr[2][2][4];

    #define SC_LOAD(st, itv)                                                     \
        do {                                                                     \
            uint32_t a0 = sb + (st) * SC_STAGE;                                  \
            uint32_t b0 = a0 + SC_BOFF;                                          \
            int kb = (itv) * 64;                                                 \
            for (int i = tid; i < 2048; i += 192) {                              \
                if (i < 1536) {                                                  \
                    int row = i >> 3, ch = i & 7;                                \
                    CPA(a0 + (row * 72 + ch * 8) * 2,                            \
                        Ab + (size_t)row * C_ + kb + ch * 8);                    \
                } else {                                                         \
                    int j = i - 1536;                                            \
                    int row = j >> 3, ch = j & 7;                                \
                    CPA(b0 + (row * 72 + ch * 8) * 2,                            \
                        Bb + (size_t)row * C_ + kb + ch * 8);                    \
                }                                                                \
            }                                                                    \
            CPCOMMIT();                                                          \
        } while (0)

    #define SC_FRAG(slot, aB, bB, ks)                                            \
        do {                                                                     \
            _Pragma("unroll")                                                    \
            for (int mi = 0; mi < 4; mi++)                                       \
                LDSM4(afr[slot][mi][0], afr[slot][mi][1],                        \
                      afr[slot][mi][2], afr[slot][mi][3],                        \
                      (aB) + aoff + (mi * 16 * 72 + (ks)) * 2);                  \
            _Pragma("unroll")                                                    \
            for (int bi = 0; bi < 2; bi++)                                       \
                LDSM4(bfr[slot][bi][0], bfr[slot][bi][1],                        \
                      bfr[slot][bi][2], bfr[slot][bi][3],                        \
                      (bB) + boff + (bi * 16 * 72 + (ks)) * 2);                  \
        } while (0)

    const int NK = C_ / 64;  // 24
    SC_LOAD(0, 0); SC_LOAD(1, 1);

    for (int it = 0; it < NK; ++it) {
        if (it < NK - 1) CPWAIT1();
        else             CPWAIT0();
        __syncthreads();
        int nx = it + 2;
        if (nx < NK) SC_LOAD(nx % 3, nx);

        uint32_t aB = sb + (it % 3) * SC_STAGE;
        uint32_t bB = aB + SC_BOFF;

        SC_FRAG(0, aB, bB, 0);
        #pragma unroll
        for (int ks = 0; ks < 64; ks += 16) {
            int cur = (ks >> 4) & 1;
            if (ks + 16 < 64) SC_FRAG(cur ^ 1, aB, bB, ks + 16);
            #pragma unroll
            for (int mi = 0; mi < 4; mi++)
                #pragma unroll
                for (int ni = 0; ni < 4; ni++)
                    mma16(acc[mi][ni], afr[cur][mi], &bfr[cur][ni >> 1][(ni & 1) * 2]);
        }
    }
    #undef SC_FRAG
    #undef SC_LOAD

    float* Cb = g_S + (size_t)b * M_ * N_ + (size_t)nt * 64;
    #pragma unroll
    for (int mi = 0; mi < 4; mi++)
        #pragma unroll
        for (int ni = 0; ni < 4; ni++) {
            int row = m0 + mi * 16 + g;
            int col = n0 + ni * 8 + q * 2;
            *(float2*)(Cb + (size_t)row * N_ + col)       = make_float2(acc[mi][ni][0], acc[mi][ni][1]);
            *(float2*)(Cb + (size_t)(row + 8) * N_ + col) = make_float2(acc[mi][ni][2], acc[mi][ni][3]);
        }
}

// ---------------------------------------------------------------------------
// k_softmax: masked softmax; reads g_S f32, writes g_P16 fp16
// ---------------------------------------------------------------------------
__global__ __launch_bounds__(256) void k_softmax(const int* __restrict__ mask) {
    int row = blockIdx.x;
    int b = row / M_, m = row % M_, r = m & 7;
    const float* S = g_S + (size_t)row * N_;
    __half* P = g_P16 + (size_t)row * N_;
    const int* mrow = mask + ((size_t)(b * R_ + r)) * (N_ - R_);
    int tid = threadIdx.x;

    float vals[16];
    float mx = -1e30f;
    #pragma unroll
    for (int i = 0; i < 16; i++) {
        int n = i * 256 + tid;
        float s = S[n];
        bool valid = (n < R_) ? (n == r) : (mrow[n - R_] != 0);
        s = valid ? s : -1e30f;
        vals[i] = s;
        mx = fmaxf(mx, s);
    }
    __shared__ float smx[8], ssm[8];
    float wmx = warpMax(mx);
    if ((tid & 31) == 0) smx[tid >> 5] = wmx;
    __syncthreads();
    float bm = smx[0];
    #pragma unroll
    for (int j = 1; j < 8; j++) bm = fmaxf(bm, smx[j]);

    float sum = 0.f;
    #pragma unroll
    for (int i = 0; i < 16; i++) {
        vals[i] = expf(vals[i] - bm);
        sum += vals[i];
    }
    float wsm = warpSum(sum);
    if ((tid & 31) == 0) ssm[tid >> 5] = wsm;
    __syncthreads();
    float tot = 0.f;
    #pragma unroll
    for (int j = 0; j < 8; j++) tot += ssm[j];
    float inv = 1.0f / tot;
    #pragma unroll
    for (int i = 0; i < 16; i++) P[i * 256 + tid] = __float2half_rn(vals[i] * inv);
}

// ---------------------------------------------------------------------------
// k_ax: AX[m,c] += sum_{n in split} P16[m,n] * x16[n,c]   (split-K x4)
// BM=192, BN=64 (c), BK=64 (tokens), 3-stage depth-2, fragment double-buffer.
// 192 threads (3m x 2n), warp 64x32. 2 CTAs/SM. grid (24 c-tiles, 4, 8).
// ---------------------------------------------------------------------------
#define AX_STAGE 36864   // A 192*72*2 + B 64*72*2
#define AX_BOFF  27648
#define AX_SPLIT 4
__global__ __launch_bounds__(192, 2) void k_ax() {
    extern __shared__ char smem[];
    uint32_t sb = (uint32_t)__cvta_generic_to_shared(smem);
    int b = blockIdx.z, nt = blockIdx.x, kc = blockIdx.y;
    int tid = threadIdx.x, lane = tid & 31, warp = tid >> 5;
    int g = lane >> 2, q = lane & 3;
    int m0 = (warp >> 1) * 64, n0 = (warp & 1) * 32;

    const int K0 = kc * (N_ / AX_SPLIT);
    const __half* Ab = g_P16 + (size_t)b * M_ * N_ + K0;
    const __half* Bx = g_x16 + (size_t)b * N_ * C_ + (size_t)K0 * C_ + nt * 64;

    const uint32_t aoff = (uint32_t)((m0 + (lane & 7) + ((lane >> 3) & 1) * 8) * 72
                                     + (lane >> 4) * 8) * 2;
    // trans B: rows = k (tokens), cols = n
    const uint32_t boff = (uint32_t)(((lane & 7) + ((lane >> 3) & 1) * 8) * 72
                                     + n0 + ((lane >> 4) & 1) * 8) * 2;

    float acc[4][4][4] = {};
    uint32_t afr[2][4][4], bfr[2][2][4];

    #define AX_LOAD(st, itv)                                                     \
        do {                                                                     \
            uint32_t a0 = sb + (st) * AX_STAGE;                                  \
            uint32_t b0 = a0 + AX_BOFF;                                          \
            int kb = (itv) * 64;                                                 \
            for (int i = tid; i < 2048; i += 192) {                              \
                if (i < 1536) {                                                  \
                    int row = i >> 3, ch = i & 7;                                \
                    CPA(a0 + (row * 72 + ch * 8) * 2,                            \
                        Ab + (size_t)row * N_ + kb + ch * 8);                    \
                } else {                                                         \
                    int j = i - 1536;                                            \
                    int row = j >> 3, ch = j & 7;                                \
                    CPA(b0 + (row * 72 + ch * 8) * 2,                            \
                        Bx + (size_t)(kb + row) * C_ + ch * 8);                  \
                }                                                                \
            }                                                                    \
            CPCOMMIT();                                                          \
        } while (0)

    #define AX_FRAG(slot, aB, bB, ks)                                            \
        do {                                                                     \
            _Pragma("unroll")                                                    \
            for (int mi = 0; mi < 4; mi++)                                       \
                LDSM4(afr[slot][mi][0], afr[slot][mi][1],                        \
                      afr[slot][mi][2], afr[slot][mi][3],                        \
                      (aB) + aoff + (mi * 16 * 72 + (ks)) * 2);                  \
            _Pragma("unroll")                                                    \
            for (int bi = 0; bi < 2; bi++)                                       \
                LDSM4T(bfr[slot][bi][0], bfr[slot][bi][1],                       \
                       bfr[slot][bi][2], bfr[slot][bi][3],                       \
                       (bB) + boff + ((ks) * 72 + bi * 16) * 2);                 \
        } while (0)

    const int NK = (N_ / AX_SPLIT) / 64;  // 16
    AX_LOAD(0, 0); AX_LOAD(1, 1);

    for (int it = 0; it < NK; ++it) {
        if (it < NK - 1) CPWAIT1();
        else             CPWAIT0();
        __syncthreads();
        int nx = it + 2;
        if (nx < NK) AX_LOAD(nx % 3, nx);

        uint32_t aB = sb + (it % 3) * AX_STAGE;
        uint32_t bB = aB + AX_BOFF;

        AX_FRAG(0, aB, bB, 0);
        #pragma unroll
        for (int ks = 0; ks < 64; ks += 16) {
            int cur = (ks >> 4) & 1;
            if (ks + 16 < 64) AX_FRAG(cur ^ 1, aB, bB, ks + 16);
            #pragma unroll
            for (int mi = 0; mi < 4; mi++)
                #pragma unroll
                for (int ni = 0; ni < 4; ni++)
                    mma16(acc[mi][ni], afr[cur][mi], &bfr[cur][ni >> 1][(ni & 1) * 2]);
        }
    }
    #undef AX_FRAG
    #undef AX_LOAD

    float* Cb = g_AX + (size_t)b * M_ * C_ + nt * 64;
    #pragma unroll
    for (int mi = 0; mi < 4; mi++)
        #pragma unroll
        for (int ni = 0; ni < 4; ni++) {
            int row = m0 + mi * 16 + g;
            int col = n0 + ni * 8 + q * 2;
            float* p0 = Cb + (size_t)row * C_ + col;
            float* p1 = Cb + (size_t)(row + 8) * C_ + col;
            atomicAdd(p0,     acc[mi][ni][0]);
            atomicAdd(p0 + 1, acc[mi][ni][1]);
            atomicAdd(p1,     acc[mi][ni][2]);
            atomicAdd(p1 + 1, acc[mi][ni][3]);
        }
}

// ---------------------------------------------------------------------------
// k_d1: XCLS[b,r,cc] += sum_{c in slice} AX[b, (cc/64)*8+r, c] * Wv[cc, c]
// K-split x16: grid (6, 8, 16). atomicAdd into zeroed g_XCLS.
// ---------------------------------------------------------------------------
__global__ __launch_bounds__(256) void k_d1(const float* __restrict__ Wv) {
    int b = blockIdx.y, kc = blockIdx.z, t = threadIdx.x;
    int k0 = kc * QK_SLICE;
    int cc = blockIdx.x * 256 + t;
    int h = cc >> 6;
    const float4* wr = (const float4*)(Wv + (size_t)cc * C_ + k0);
    const float4* ax[R_];
    #pragma unroll
    for (int r = 0; r < R_; r++)
        ax[r] = (const float4*)(g_AX + ((size_t)b * M_ + h * 8 + r) * C_ + k0);
    float acc[R_] = {};
    #pragma unroll 4
    for (int k4 = 0; k4 < QK_SLICE / 4; k4++) {
        float4 w = wr[k4];
        #pragma unroll
        for (int r = 0; r < R_; r++) {
            float4 a = ax[r][k4];
            acc[r] += a.x * w.x + a.y * w.y + a.z * w.z + a.w * w.w;
        }
    }
    #pragma unroll
    for (int r = 0; r < R_; r++)
        atomicAdd(&g_XCLS[(b * R_ + r) * C_ + cc], acc[r]);
}

// ---------------------------------------------------------------------------
// k_d2: out[b,r,c'] += sum_{cc in slice} XCLS[b,r,cc] * Wp[c',cc]  (+bias on kc0)
// K-split x16: grid (6, 8, 16). atomicAdd into zeroed out.
// ---------------------------------------------------------------------------
__global__ __launch_bounds__(256) void k_d2(const float* __restrict__ Wp,
                                            const float* __restrict__ bp,
                                            float* __restrict__ out) {
    int b = blockIdx.y, kc = blockIdx.z, t = threadIdx.x;
    int k0 = kc * QK_SLICE;
    int cp = blockIdx.x * 256 + t;
    const float4* wr = (const float4*)(Wp + (size_t)cp * C_ + k0);
    const float4* xc[R_];
    #pragma unroll
    for (int r = 0; r < R_; r++)
        xc[r] = (const float4*)(g_XCLS + (size_t)(b * R_ + r) * C_ + k0);
    float acc[R_] = {};
    #pragma unroll 4
    for (int k4 = 0; k4 < QK_SLICE / 4; k4++) {
        float4 w = wr[k4];
        #pragma unroll
        for (int r = 0; r < R_; r++) {
            float4 a = xc[r][k4];
            acc[r] += a.x * w.x + a.y * w.y + a.z * w.z + a.w * w.w;
        }
    }
    float bias = (kc == 0) ? bp[cp] : 0.f;
    #pragma unroll
    for (int r = 0; r < R_; r++)
        atomicAdd(&out[((size_t)(b * R_ + r)) * C_ + cp], acc[r] + bias);
}

// ---------------------------------------------------------------------------
// launch
// ---------------------------------------------------------------------------
extern "C" void kernel_launch(void* const* d_in, const int* in_sizes, int n_in,
                              void* d_out, int out_size) {
    const float* x    = (const float*)d_in[0];
    const int*   mask = (const int*)d_in[1];
    const float* Wq   = (const float*)d_in[2];
    const float* Wk   = (const float*)d_in[3];
    const float* Wv   = (const float*)d_in[4];
    const float* Wp   = (const float*)d_in[5];
    const float* bp   = (const float*)d_in[6];
    float* out = (float*)d_out;

    const int SC_SMEM = 3 * SC_STAGE;  // 110592
    const int AX_SMEM = 3 * AX_STAGE;  // 110592
    cudaFuncSetAttribute(k_scores, cudaFuncAttributeMaxDynamicSharedMemorySize, SC_SMEM);
    cudaFuncSetAttribute(k_ax,     cudaFuncAttributeMaxDynamicSharedMemorySize, AX_SMEM);

    k_p2     <<<P2_CONV + P2_Q + P2_Z, 256>>>(x, Wq, out);
    k_p3     <<<P3_CONV + 576, 256>>>(x, Wk);
    k_scores <<<dim3(N_ / 64, 1, B_), 192, SC_SMEM>>>();
    k_softmax<<<B_ * M_, 256>>>(mask);
    k_ax     <<<dim3(C_ / 64, AX_SPLIT, B_), 192, AX_SMEM>>>();
    k_d1     <<<dim3(C_ / 256, B_, 16), 256>>>(Wv);
    k_d2     <<<dim3(C_ / 256, B_, 16), 256>>>(Wp, bp, out);
}